// round 15
// baseline (speedup 1.0000x reference)
#include <cuda_runtime.h>
#include <cuda_fp16.h>
#include <math.h>
#include <cstdint>

// ---------------------------------------------------------------------------
// Problem constants
// ---------------------------------------------------------------------------
#define B 8
#define SEQ 1024
#define WIN 9
#define D 512
#define DFF 1024
#define VOCAB 16384
#define NTOK (B * SEQ)   // 8192
#define EPS 1e-5f

// ---------------------------------------------------------------------------
// Scratch buffers (device globals: no allocation allowed)
// ---------------------------------------------------------------------------
__device__ float  g_h0  [NTOK * D];        // embed+pos, fp32 (residual)
__device__ __half g_h0h [NTOK * D];        // fp16 copy (QKV GEMM input)
__device__ float  g_qkv [NTOK * 3 * D];    // fused QKV output (fp32)
__device__ __half g_atth[NTOK * D];        // attention out (O-proj input)
__device__ float  g_o   [NTOK * D];        // O-proj + h0 (residual fused)
__device__ float  g_h1  [NTOK * D];
__device__ __half g_h1h [NTOK * D];
__device__ __half g_midh[NTOK * DFF];
__device__ float  g_f   [NTOK * D];        // FFN2 + h1 (residual fused)
__device__ __half g_h2h [NTOK * D];
// transposed fp16 weights ([N,K] K-major)
__device__ __half g_Wqkv[3 * D * D];
__device__ __half g_WoT [D * D];
__device__ __half g_W1T [DFF * D];
__device__ __half g_W2T [D * DFF];
__device__ __half g_WhT [VOCAB * D];
__device__ float  g_bqkv[3 * D];

// ---------------------------------------------------------------------------
// helpers (plain compute_103-legal PTX)
// ---------------------------------------------------------------------------
__device__ __forceinline__ uint32_t smem_to_u32(const void* p) {
    uint32_t a;
    asm("{ .reg .u64 t; cvta.to.shared.u64 t, %1; cvt.u32.u64 %0, t; }" : "=r"(a) : "l"(p));
    return a;
}
__device__ __forceinline__ void cp_async16(uint32_t saddr, const void* gptr) {
    asm volatile("cp.async.cg.shared.global [%0], [%1], 16;" :: "r"(saddr), "l"(gptr));
}
#define CP_COMMIT()  asm volatile("cp.async.commit_group;" ::: "memory")
#define CP_WAIT(n)   asm volatile("cp.async.wait_group %0;" :: "n"(n) : "memory")

__device__ __forceinline__ void ldsm_x4(uint32_t* d, uint32_t addr) {
    asm volatile("ldmatrix.sync.aligned.m8n8.x4.shared.b16 {%0,%1,%2,%3}, [%4];"
        : "=r"(d[0]), "=r"(d[1]), "=r"(d[2]), "=r"(d[3]) : "r"(addr));
}
__device__ __forceinline__ void mma_f16(float* d, const uint32_t* a, const uint32_t* b) {
    asm volatile(
        "mma.sync.aligned.m16n8k16.row.col.f32.f16.f16.f32 "
        "{%0,%1,%2,%3}, {%4,%5,%6,%7}, {%8,%9}, {%0,%1,%2,%3};"
        : "+f"(d[0]), "+f"(d[1]), "+f"(d[2]), "+f"(d[3])
        : "r"(a[0]), "r"(a[1]), "r"(a[2]), "r"(a[3]),
          "r"(b[0]), "r"(b[1]));
}

// ---------------------------------------------------------------------------
// Kernel: batched QKV transpose: z selects Wq/Wk/Wv -> Wqkv rows z*D..
// ---------------------------------------------------------------------------
__global__ void qkv_transpose(const float* __restrict__ Wq,
                              const float* __restrict__ Wk,
                              const float* __restrict__ Wv,
                              __half* __restrict__ out) {
    __shared__ float t[32][33];
    const float* in = (blockIdx.z == 0) ? Wq : (blockIdx.z == 1) ? Wk : Wv;
    __half* o = out + (size_t)blockIdx.z * D * D;
    int bx = blockIdx.x * 32, by = blockIdx.y * 32;
    int x = bx + threadIdx.x;
    int y = by + threadIdx.y;
#pragma unroll
    for (int i = 0; i < 32; i += 8)
        t[threadIdx.y + i][threadIdx.x] = in[(size_t)(y + i) * D + x];
    __syncthreads();
    x = by + threadIdx.x;
    y = bx + threadIdx.y;
#pragma unroll
    for (int i = 0; i < 32; i += 8)
        o[(size_t)(y + i) * D + x] = __float2half_rn(t[threadIdx.x][threadIdx.y + i]);
}

// ---------------------------------------------------------------------------
// Kernel: merged weight transposes (Wo, W1, W2, Wh) -> fp16 [N,K]
// block ranges: [0,256) Wo | [256,768) W1 | [768,1280) W2 | [1280,9472) Wh
// ---------------------------------------------------------------------------
__global__ void prep_weights(const float* __restrict__ Wo, const float* __restrict__ W1,
                             const float* __restrict__ W2, const float* __restrict__ Wh,
                             __half* __restrict__ WoT, __half* __restrict__ W1T,
                             __half* __restrict__ W2T, __half* __restrict__ WhT) {
    __shared__ float t[32][33];
    int bid = blockIdx.x;
    const float* in; __half* out; int R, Cn, loc;
    if (bid < 256)       { in = Wo; out = WoT; R = D;   Cn = D;     loc = bid; }
    else if (bid < 768)  { in = W1; out = W1T; R = D;   Cn = DFF;   loc = bid - 256; }
    else if (bid < 1280) { in = W2; out = W2T; R = DFF; Cn = D;     loc = bid - 768; }
    else                 { in = Wh; out = WhT; R = D;   Cn = VOCAB; loc = bid - 1280; }
    int gx = Cn >> 5;
    int bx = (loc % gx) * 32, by = (loc / gx) * 32;
    int x = bx + threadIdx.x;
    int y = by + threadIdx.y;
#pragma unroll
    for (int i = 0; i < 32; i += 8)
        t[threadIdx.y + i][threadIdx.x] = in[(size_t)(y + i) * Cn + x];
    __syncthreads();
    x = by + threadIdx.x;
    y = bx + threadIdx.y;
#pragma unroll
    for (int i = 0; i < 32; i += 8)
        out[(size_t)(y + i) * R + x] = __float2half_rn(t[threadIdx.x][threadIdx.y + i]);
}

// ---------------------------------------------------------------------------
// Kernel: fp16 mma.sync GEMM  C[M,N] = A[M,K] @ Bt[N,K]^T + bias (+ReLU)(+Radd)
// CTA tile 128x128, BK=64 halves, 256 threads (8 warps 2x4), warp tile 64x32,
// 3-stage cp.async pipeline (96KB smem -> 2 CTAs/SM), XOR swizzle, ldmatrix.
// ---------------------------------------------------------------------------
#define GBM 128
#define GBN 128
#define STAGES 3
#define NTHR 256
#define STAGE_AB (GBM * 128)   // bytes per A stage (128 rows x 128B)
#define STAGE_BB (GBN * 128)   // bytes per B stage

__global__ __launch_bounds__(NTHR, 2) void gemm_tc(
    const __half* __restrict__ A, const __half* __restrict__ Bt,
    const float* __restrict__ bias, float* __restrict__ Cf, __half* __restrict__ Ch,
    const float* __restrict__ Radd,
    int M, int N, int K, int relu)
{
    extern __shared__ uint32_t smem[];
    const uint32_t sA_u32 = smem_to_u32(smem);
    const uint32_t sB_u32 = sA_u32 + STAGES * STAGE_AB;

    const int tid  = threadIdx.x;
    const int lane = tid & 31;
    const int wid  = tid >> 5;
    const int wm   = wid >> 2;           // 0..1  (M warps, 64 rows each)
    const int wn   = wid & 3;            // 0..3  (N warps, 32 cols each)
    const int bm   = blockIdx.y * GBM;
    const int bn   = blockIdx.x * GBN;
    const int nk   = K >> 6;             // 64 halves per chunk

    // cp.async per-thread coordinates (A: 4 x 16B, B: 4 x 16B per chunk)
    int ar[4], ac[4]; uint32_t aso[4];
#pragma unroll
    for (int t = 0; t < 4; t++) {
        int idx = t * NTHR + tid;        // 0..1023 = 128 rows x 8 groups
        ar[t] = idx >> 3; ac[t] = idx & 7;
        aso[t] = (uint32_t)(ar[t] * 128 + ((ac[t] ^ (ar[t] & 7)) << 4));
    }

    // ldmatrix per-thread constants
    uint32_t aRowB[4], aR7[4];
#pragma unroll
    for (int mf = 0; mf < 4; mf++) {
        int r = wm * 64 + mf * 16 + (lane & 15);
        aRowB[mf] = (uint32_t)r * 128u;
        aR7[mf]   = (uint32_t)(r & 7);
    }
    const uint32_t gselA = (lane >> 4) & 1;
    uint32_t bRowB[2], bR7[2];
#pragma unroll
    for (int np = 0; np < 2; np++) {
        int r = wn * 32 + np * 16 + (lane & 7) + ((lane >> 4) << 3);
        bRowB[np] = (uint32_t)r * 128u;
        bR7[np]   = (uint32_t)(r & 7);
    }
    const uint32_t gselB = (lane >> 3) & 1;

    float acc[4][4][4];
#pragma unroll
    for (int i = 0; i < 4; i++)
#pragma unroll
        for (int j = 0; j < 4; j++)
#pragma unroll
            for (int l = 0; l < 4; l++) acc[i][j][l] = 0.0f;

#define LOAD_STAGE(chunk, stage) do { \
    const int _kc = (chunk) << 6; \
    const uint32_t _sa = sA_u32 + (uint32_t)(stage) * STAGE_AB; \
    const uint32_t _sb = sB_u32 + (uint32_t)(stage) * STAGE_BB; \
    _Pragma("unroll") \
    for (int _t = 0; _t < 4; _t++) \
        cp_async16(_sa + aso[_t], A + (size_t)(bm + ar[_t]) * K + _kc + ac[_t] * 8); \
    _Pragma("unroll") \
    for (int _t = 0; _t < 4; _t++) \
        cp_async16(_sb + aso[_t], Bt + (size_t)(bn + ar[_t]) * K + _kc + ac[_t] * 8); \
    CP_COMMIT(); \
} while (0)

    // prologue: stages 0..1   (nk >= 8 at every call site)
    LOAD_STAGE(0, 0);
    LOAD_STAGE(1, 1);

    int cur = 0, nxt = 2;   // stage holding 'chunk'; stage receiving 'chunk+2'
    for (int chunk = 0; chunk < nk; chunk++) {
        CP_WAIT(STAGES - 2);
        __syncthreads();

        if (chunk + 2 < nk) {
            LOAD_STAGE(chunk + 2, nxt);
        } else {
            CP_COMMIT();
        }

        const uint32_t saBase = sA_u32 + (uint32_t)cur * STAGE_AB;
        const uint32_t sbBase = sB_u32 + (uint32_t)cur * STAGE_BB;

#pragma unroll
        for (int ks = 0; ks < 4; ks++) {          // 4 x K=16 per 64-chunk
            const uint32_t gA = 2 * ks + gselA;
            const uint32_t gB = 2 * ks + gselB;
            uint32_t af[4][4];
#pragma unroll
            for (int mf = 0; mf < 4; mf++)
                ldsm_x4(af[mf], saBase + aRowB[mf] + ((gA ^ aR7[mf]) << 4));
            uint32_t bq[2][4];
#pragma unroll
            for (int np = 0; np < 2; np++)
                ldsm_x4(bq[np], sbBase + bRowB[np] + ((gB ^ bR7[np]) << 4));
#pragma unroll
            for (int mf = 0; mf < 4; mf++)
#pragma unroll
                for (int nf = 0; nf < 4; nf++)
                    mma_f16(acc[mf][nf], af[mf], &bq[nf >> 1][(nf & 1) * 2]);
        }
        cur = (cur == 2) ? 0 : cur + 1;
        nxt = (nxt == 2) ? 0 : nxt + 1;
    }

    // ---- epilogue ----
#pragma unroll
    for (int mf = 0; mf < 4; mf++) {
        int row0 = bm + wm * 64 + mf * 16 + (lane >> 2);
#pragma unroll
        for (int nf = 0; nf < 4; nf++) {
            int col = bn + wn * 32 + nf * 8 + (lane & 3) * 2;
            float bx = bias[col], by = bias[col + 1];
            float2 v0, v1;
            v0.x = acc[mf][nf][0] + bx; v0.y = acc[mf][nf][1] + by;
            v1.x = acc[mf][nf][2] + bx; v1.y = acc[mf][nf][3] + by;
            if (relu) {
                v0.x = fmaxf(v0.x, 0.0f); v0.y = fmaxf(v0.y, 0.0f);
                v1.x = fmaxf(v1.x, 0.0f); v1.y = fmaxf(v1.y, 0.0f);
            }
            if (Radd) {
                float2 r0 = *(const float2*)(Radd + (size_t)row0 * N + col);
                float2 r1 = *(const float2*)(Radd + (size_t)(row0 + 8) * N + col);
                v0.x += r0.x; v0.y += r0.y;
                v1.x += r1.x; v1.y += r1.y;
            }
            if (Cf) {
                *(float2*)(Cf + (size_t)row0 * N + col)       = v0;
                *(float2*)(Cf + (size_t)(row0 + 8) * N + col) = v1;
            } else {
                *(__half2*)(Ch + (size_t)row0 * N + col)       = __floats2half2_rn(v0.x, v0.y);
                *(__half2*)(Ch + (size_t)(row0 + 8) * N + col) = __floats2half2_rn(v1.x, v1.y);
            }
        }
    }
}

// ---------------------------------------------------------------------------
// Kernel: embedding + 2D pos (fp32 + fp16 outputs) and QKV bias concat
// grid = NTOK + 12; blocks >= NTOK handle the 1536-entry bias concat
// ---------------------------------------------------------------------------
__global__ void embed_kernel(const int* __restrict__ x,
                             const float* __restrict__ tab,
                             const float* __restrict__ rowe,
                             const float* __restrict__ cole,
                             const float* __restrict__ bq,
                             const float* __restrict__ bk,
                             const float* __restrict__ bv,
                             float* __restrict__ h,
                             __half* __restrict__ hh,
                             float* __restrict__ bqkv) {
    int qi = blockIdx.x;
    if (qi >= NTOK) {
        int i = (qi - NTOK) * 128 + threadIdx.x;
        if (i < 3 * D)
            bqkv[i] = (i < D) ? bq[i] : (i < 2 * D) ? bk[i - D] : bv[i - 2 * D];
        return;
    }
    int s  = qi & (SEQ - 1);
    int r  = s >> 5, c = s & 31;
    int tok = x[qi];
    int d = threadIdx.x * 4;

    float4 e = *(const float4*)&tab[(size_t)tok * D + d];
    float4 p;
    if (d < D / 2) p = *(const float4*)&rowe[r * (D / 2) + d];
    else           p = *(const float4*)&cole[c * (D / 2) + (d - D / 2)];
    e.x += p.x; e.y += p.y; e.z += p.z; e.w += p.w;
    *(float4*)&h[(size_t)qi * D + d] = e;
    *(__half2*)&hh[(size_t)qi * D + d]     = __floats2half2_rn(e.x, e.y);
    *(__half2*)&hh[(size_t)qi * D + d + 2] = __floats2half2_rn(e.z, e.w);
}

// ---------------------------------------------------------------------------
// Kernel: fused local-causal attention over fused QKV buffer (stride 3D)
// 256 threads (8 warps): score phase 8-way, AV phase float2/thread with
// 2-way unrolled dual accumulators. Output fp16.
// ---------------------------------------------------------------------------
__global__ void attn_kernel(const float* __restrict__ QKV,
                            __half* __restrict__ O) {
    int qi = blockIdx.x;
    int b = qi >> 10, s = qi & (SEQ - 1);
    int r = s >> 5, c = s & 31;
    int r0 = (r - WIN < 0) ? 0 : r - WIN;
    int c0 = (c - WIN < 0) ? 0 : c - WIN;
    int c1 = (c + WIN > 31) ? 31 : c + WIN;
    int wcols = c1 - c0 + 1;
    int nfull = r - r0;
    int nk = nfull * wcols + (c - c0 + 1);

    __shared__ float qv[D];
    __shared__ float sc[256];
    __shared__ int   kid[256];
    __shared__ float red[8];

    int tid = threadIdx.x;                // 0..255
    int lane = tid & 31, wid = tid >> 5;  // 8 warps

    // stage q row (256 threads x float2)
    *(float2*)&qv[tid * 2] = *(const float2*)&QKV[(size_t)qi * (3 * D) + tid * 2];
    __syncthreads();

    const float scale = 0.044194173824159216f;
    const float* kbase = QKV + (size_t)b * SEQ * (3 * D) + D;

    // scores: warp w handles keys w, w+8, ...
    for (int j = wid; j < nk; j += 8) {
        int row, col;
        if (j < nfull * wcols) { row = r0 + j / wcols; col = c0 + j % wcols; }
        else                   { row = r;             col = c0 + (j - nfull * wcols); }
        int kk = row * 32 + col;
        const float* krow = kbase + (size_t)kk * (3 * D);
        float sum = 0.0f;
#pragma unroll
        for (int t = 0; t < D / 32; t++)
            sum = fmaf(qv[lane + 32 * t], krow[lane + 32 * t], sum);
#pragma unroll
        for (int off = 16; off; off >>= 1)
            sum += __shfl_xor_sync(0xffffffffu, sum, off);
        if (lane == 0) { sc[j] = sum * scale; kid[j] = kk; }
    }
    __syncthreads();

    // block max (8 warps)
    float m = -1e30f;
    for (int j = tid; j < nk; j += 256) m = fmaxf(m, sc[j]);
#pragma unroll
    for (int off = 16; off; off >>= 1)
        m = fmaxf(m, __shfl_xor_sync(0xffffffffu, m, off));
    if (lane == 0) red[wid] = m;
    __syncthreads();
    m = red[0];
#pragma unroll
    for (int w = 1; w < 8; w++) m = fmaxf(m, red[w]);

    // exp + sum
    float ssum = 0.0f;
    for (int j = tid; j < nk; j += 256) {
        float e = __expf(sc[j] - m);
        sc[j] = e;
        ssum += e;
    }
    __syncthreads();
#pragma unroll
    for (int off = 16; off; off >>= 1)
        ssum += __shfl_xor_sync(0xffffffffu, ssum, off);
    if (lane == 0) red[wid] = ssum;
    __syncthreads();
    float tot = red[0];
#pragma unroll
    for (int w = 1; w < 8; w++) tot += red[w];
    float inv = 1.0f / tot;

    // AV: thread owns dims [2*tid, 2*tid+2); 2-way unrolled dual accumulators
    const float* vbase = QKV + (size_t)b * SEQ * (3 * D) + 2 * D;
    int d = tid * 2;
    float2 a0 = make_float2(0.f, 0.f);
    float2 a1 = make_float2(0.f, 0.f);
    int j = 0;
    for (; j + 1 < nk; j += 2) {
        float w0 = sc[j], w1 = sc[j + 1];
        float2 v0 = *(const float2*)&vbase[(size_t)kid[j]     * (3 * D) + d];
        float2 v1 = *(const float2*)&vbase[(size_t)kid[j + 1] * (3 * D) + d];
        a0.x = fmaf(w0, v0.x, a0.x); a0.y = fmaf(w0, v0.y, a0.y);
        a1.x = fmaf(w1, v1.x, a1.x); a1.y = fmaf(w1, v1.y, a1.y);
    }
    if (j < nk) {
        float w0 = sc[j];
        float2 v0 = *(const float2*)&vbase[(size_t)kid[j] * (3 * D) + d];
        a0.x = fmaf(w0, v0.x, a0.x); a0.y = fmaf(w0, v0.y, a0.y);
    }
    a0.x = (a0.x + a1.x) * inv;
    a0.y = (a0.y + a1.y) * inv;
    *(__half2*)&O[(size_t)qi * D + d] = __floats2half2_rn(a0.x, a0.y);
}

// ---------------------------------------------------------------------------
// Kernel: LayerNorm(X) * g + b  ->  fp32 out (optional) + fp16 out (optional)
// ---------------------------------------------------------------------------
__global__ void ln_kernel(const float* __restrict__ X,
                          const float* __restrict__ g,
                          const float* __restrict__ beta,
                          float* __restrict__ outf,
                          __half* __restrict__ outh) {
    int row = blockIdx.x;
    int tid = threadIdx.x;
    int lane = tid & 31, wid = tid >> 5;
    __shared__ float reds[4], redq[4];

    int d = tid * 4;
    float4 xv = *(const float4*)&X[(size_t)row * D + d];

    float s  = xv.x + xv.y + xv.z + xv.w;
    float sq = xv.x * xv.x + xv.y * xv.y + xv.z * xv.z + xv.w * xv.w;
#pragma unroll
    for (int off = 16; off; off >>= 1) {
        s  += __shfl_xor_sync(0xffffffffu, s,  off);
        sq += __shfl_xor_sync(0xffffffffu, sq, off);
    }
    if (lane == 0) { reds[wid] = s; redq[wid] = sq; }
    __syncthreads();
    s  = reds[0] + reds[1] + reds[2] + reds[3];
    sq = redq[0] + redq[1] + redq[2] + redq[3];

    float mu  = s * (1.0f / D);
    float var = sq * (1.0f / D) - mu * mu;
    float rstd = rsqrtf(var + EPS);

    float4 gv = *(const float4*)&g[d];
    float4 bv = *(const float4*)&beta[d];
    float4 o;
    o.x = (xv.x - mu) * rstd * gv.x + bv.x;
    o.y = (xv.y - mu) * rstd * gv.y + bv.y;
    o.z = (xv.z - mu) * rstd * gv.z + bv.z;
    o.w = (xv.w - mu) * rstd * gv.w + bv.w;
    if (outf) *(float4*)&outf[(size_t)row * D + d] = o;
    if (outh) {
        *(__half2*)&outh[(size_t)row * D + d]     = __floats2half2_rn(o.x, o.y);
        *(__half2*)&outh[(size_t)row * D + d + 2] = __floats2half2_rn(o.z, o.w);
    }
}

// ---------------------------------------------------------------------------
// Launch — single stream; attn_kernel at launch index 3 for ncu capture.
// Order: qkv_transpose(0), embed(1), QKV GEMM(2), attn(3), prep_weights(4),
//        O-proj(5), LN1(6), FFN1(7), FFN2(8), LN2(9), head(10)
// ---------------------------------------------------------------------------
extern "C" void kernel_launch(void* const* d_in, const int* in_sizes, int n_in,
                              void* d_out, int out_size) {
    const int*   x     = (const int*)  d_in[0];
    const float* tab   = (const float*)d_in[1];
    const float* rowe  = (const float*)d_in[2];
    const float* cole  = (const float*)d_in[3];
    const float* Wq    = (const float*)d_in[4];
    const float* bq    = (const float*)d_in[5];
    const float* Wk    = (const float*)d_in[6];
    const float* bk    = (const float*)d_in[7];
    const float* Wv    = (const float*)d_in[8];
    const float* bv    = (const float*)d_in[9];
    const float* Wo    = (const float*)d_in[10];
    const float* bo    = (const float*)d_in[11];
    const float* ln1g  = (const float*)d_in[12];
    const float* ln1b  = (const float*)d_in[13];
    const float* W1    = (const float*)d_in[14];
    const float* b1    = (const float*)d_in[15];
    const float* W2    = (const float*)d_in[16];
    const float* b2    = (const float*)d_in[17];
    const float* ln2g  = (const float*)d_in[18];
    const float* ln2b  = (const float*)d_in[19];
    const float* Wh    = (const float*)d_in[20];
    const float* bh    = (const float*)d_in[21];
    float* out = (float*)d_out;

    float *h0, *qkv, *o, *h1, *f, *bqkv;
    __half *h0h, *atth, *h1h, *midh, *h2h;
    __half *Wqkv, *WoT, *W1T, *W2T, *WhT;
    cudaGetSymbolAddress((void**)&h0,   g_h0);
    cudaGetSymbolAddress((void**)&h0h,  g_h0h);
    cudaGetSymbolAddress((void**)&qkv,  g_qkv);
    cudaGetSymbolAddress((void**)&atth, g_atth);
    cudaGetSymbolAddress((void**)&o,    g_o);
    cudaGetSymbolAddress((void**)&h1,   g_h1);
    cudaGetSymbolAddress((void**)&h1h,  g_h1h);
    cudaGetSymbolAddress((void**)&midh, g_midh);
    cudaGetSymbolAddress((void**)&f,    g_f);
    cudaGetSymbolAddress((void**)&h2h,  g_h2h);
    cudaGetSymbolAddress((void**)&Wqkv, g_Wqkv);
    cudaGetSymbolAddress((void**)&WoT,  g_WoT);
    cudaGetSymbolAddress((void**)&W1T,  g_W1T);
    cudaGetSymbolAddress((void**)&W2T,  g_W2T);
    cudaGetSymbolAddress((void**)&WhT,  g_WhT);
    cudaGetSymbolAddress((void**)&bqkv, g_bqkv);

    const int GEMM_SMEM = STAGES * (STAGE_AB + STAGE_BB);  // 98304 bytes
    static int attr_set = 0;
    if (!attr_set) {
        cudaFuncSetAttribute(gemm_tc, cudaFuncAttributeMaxDynamicSharedMemorySize, GEMM_SMEM);
        attr_set = 1;
    }

    dim3 tb(32, 8);

    // 0: QKV weight transpose
    qkv_transpose<<<dim3(16, 16, 3), tb>>>(Wq, Wk, Wv, Wqkv);
    // 1: embed (+ bias concat)
    embed_kernel<<<NTOK + 12, 128>>>(x, tab, rowe, cole, bq, bk, bv, h0, h0h, bqkv);
    // 2: fused QKV GEMM -> fp32 output
    gemm_tc<<<dim3(3 * D / GBN, NTOK / GBM), NTHR, GEMM_SMEM>>>(
        h0h, Wqkv, bqkv, qkv, nullptr, nullptr, NTOK, 3 * D, D, 0);
    // 3: attention (profiled this round)
    attn_kernel<<<NTOK, 256>>>(qkv, atth);
    // 4: remaining weight transposes
    prep_weights<<<9472, tb>>>(Wo, W1, W2, Wh, WoT, W1T, W2T, WhT);
    // 5: O projection with fused residual (+ h0)
    gemm_tc<<<dim3(D / GBN, NTOK / GBM), NTHR, GEMM_SMEM>>>(
        atth, WoT, bo, o, nullptr, h0, NTOK, D, D, 0);
    // 6: LN1 -> fp32 h1 (residual for LN2) + fp16 h1h
    ln_kernel<<<NTOK, 128>>>(o, ln1g, ln1b, h1, h1h);
    // 7-8: FFN (FFN2 fuses + h1)
    gemm_tc<<<dim3(DFF / GBN, NTOK / GBM), NTHR, GEMM_SMEM>>>(
        h1h, W1T, b1, nullptr, midh, nullptr, NTOK, DFF, D, 1);
    gemm_tc<<<dim3(D / GBN, NTOK / GBM), NTHR, GEMM_SMEM>>>(
        midh, W2T, b2, f, nullptr, h1, NTOK, D, DFF, 0);
    // 9: LN2 -> fp16 only
    ln_kernel<<<NTOK, 128>>>(f, ln2g, ln2b, nullptr, h2h);
    // 10: vocab head -> d_out
    gemm_tc<<<dim3(VOCAB / GBN, NTOK / GBM), NTHR, GEMM_SMEM>>>(
        h2h, WhT, bh, out, nullptr, nullptr, NTOK, VOCAB, D, 0);
}

// round 16
// speedup vs baseline: 1.1117x; 1.1117x over previous
#include <cuda_runtime.h>
#include <cuda_fp16.h>
#include <math.h>
#include <cstdint>

// ---------------------------------------------------------------------------
// Problem constants
// ---------------------------------------------------------------------------
#define B 8
#define SEQ 1024
#define WIN 9
#define D 512
#define DFF 1024
#define VOCAB 16384
#define NTOK (B * SEQ)   // 8192
#define EPS 1e-5f

// ---------------------------------------------------------------------------
// Scratch buffers (device globals: no allocation allowed)
// ---------------------------------------------------------------------------
__device__ float  g_h0  [NTOK * D];        // embed+pos, fp32 (residual)
__device__ __half g_h0h [NTOK * D];        // fp16 copy (QKV GEMM input)
__device__ float  g_qkv [NTOK * 3 * D];    // fused QKV output (fp32)
__device__ __half g_qkvh[NTOK * 3 * D];    // fused QKV output (fp16, for AV)
__device__ __half g_atth[NTOK * D];        // attention out (O-proj input)
__device__ float  g_o   [NTOK * D];        // O-proj + h0 (residual fused)
__device__ float  g_h1  [NTOK * D];
__device__ __half g_h1h [NTOK * D];
__device__ __half g_midh[NTOK * DFF];
__device__ float  g_f   [NTOK * D];        // FFN2 + h1 (residual fused)
__device__ __half g_h2h [NTOK * D];
// transposed fp16 weights ([N,K] K-major)
__device__ __half g_Wqkv[3 * D * D];
__device__ __half g_WoT [D * D];
__device__ __half g_W1T [DFF * D];
__device__ __half g_W2T [D * DFF];
__device__ __half g_WhT [VOCAB * D];
__device__ float  g_bqkv[3 * D];

// ---------------------------------------------------------------------------
// helpers (plain compute_103-legal PTX)
// ---------------------------------------------------------------------------
__device__ __forceinline__ uint32_t smem_to_u32(const void* p) {
    uint32_t a;
    asm("{ .reg .u64 t; cvta.to.shared.u64 t, %1; cvt.u32.u64 %0, t; }" : "=r"(a) : "l"(p));
    return a;
}
__device__ __forceinline__ void cp_async16(uint32_t saddr, const void* gptr) {
    asm volatile("cp.async.cg.shared.global [%0], [%1], 16;" :: "r"(saddr), "l"(gptr));
}
#define CP_COMMIT()  asm volatile("cp.async.commit_group;" ::: "memory")
#define CP_WAIT(n)   asm volatile("cp.async.wait_group %0;" :: "n"(n) : "memory")

__device__ __forceinline__ void ldsm_x4(uint32_t* d, uint32_t addr) {
    asm volatile("ldmatrix.sync.aligned.m8n8.x4.shared.b16 {%0,%1,%2,%3}, [%4];"
        : "=r"(d[0]), "=r"(d[1]), "=r"(d[2]), "=r"(d[3]) : "r"(addr));
}
__device__ __forceinline__ void mma_f16(float* d, const uint32_t* a, const uint32_t* b) {
    asm volatile(
        "mma.sync.aligned.m16n8k16.row.col.f32.f16.f16.f32 "
        "{%0,%1,%2,%3}, {%4,%5,%6,%7}, {%8,%9}, {%0,%1,%2,%3};"
        : "+f"(d[0]), "+f"(d[1]), "+f"(d[2]), "+f"(d[3])
        : "r"(a[0]), "r"(a[1]), "r"(a[2]), "r"(a[3]),
          "r"(b[0]), "r"(b[1]));
}

// ---------------------------------------------------------------------------
// Kernel: batched QKV transpose: z selects Wq/Wk/Wv -> Wqkv rows z*D..
// ---------------------------------------------------------------------------
__global__ void qkv_transpose(const float* __restrict__ Wq,
                              const float* __restrict__ Wk,
                              const float* __restrict__ Wv,
                              __half* __restrict__ out) {
    __shared__ float t[32][33];
    const float* in = (blockIdx.z == 0) ? Wq : (blockIdx.z == 1) ? Wk : Wv;
    __half* o = out + (size_t)blockIdx.z * D * D;
    int bx = blockIdx.x * 32, by = blockIdx.y * 32;
    int x = bx + threadIdx.x;
    int y = by + threadIdx.y;
#pragma unroll
    for (int i = 0; i < 32; i += 8)
        t[threadIdx.y + i][threadIdx.x] = in[(size_t)(y + i) * D + x];
    __syncthreads();
    x = by + threadIdx.x;
    y = bx + threadIdx.y;
#pragma unroll
    for (int i = 0; i < 32; i += 8)
        o[(size_t)(y + i) * D + x] = __float2half_rn(t[threadIdx.x][threadIdx.y + i]);
}

// ---------------------------------------------------------------------------
// Kernel: merged weight transposes (Wo, W1, W2, Wh) -> fp16 [N,K]
// ---------------------------------------------------------------------------
__global__ void prep_weights(const float* __restrict__ Wo, const float* __restrict__ W1,
                             const float* __restrict__ W2, const float* __restrict__ Wh,
                             __half* __restrict__ WoT, __half* __restrict__ W1T,
                             __half* __restrict__ W2T, __half* __restrict__ WhT) {
    __shared__ float t[32][33];
    int bid = blockIdx.x;
    const float* in; __half* out; int R, Cn, loc;
    if (bid < 256)       { in = Wo; out = WoT; R = D;   Cn = D;     loc = bid; }
    else if (bid < 768)  { in = W1; out = W1T; R = D;   Cn = DFF;   loc = bid - 256; }
    else if (bid < 1280) { in = W2; out = W2T; R = DFF; Cn = D;     loc = bid - 768; }
    else                 { in = Wh; out = WhT; R = D;   Cn = VOCAB; loc = bid - 1280; }
    int gx = Cn >> 5;
    int bx = (loc % gx) * 32, by = (loc / gx) * 32;
    int x = bx + threadIdx.x;
    int y = by + threadIdx.y;
#pragma unroll
    for (int i = 0; i < 32; i += 8)
        t[threadIdx.y + i][threadIdx.x] = in[(size_t)(y + i) * Cn + x];
    __syncthreads();
    x = by + threadIdx.x;
    y = bx + threadIdx.y;
#pragma unroll
    for (int i = 0; i < 32; i += 8)
        out[(size_t)(y + i) * R + x] = __float2half_rn(t[threadIdx.x][threadIdx.y + i]);
}

// ---------------------------------------------------------------------------
// Kernel: fp16 mma.sync GEMM  C = A @ Bt^T + bias (+ReLU)(+Radd)
// Outputs: Cf (fp32) and/or Ch (fp16) — any non-null gets written.
// ---------------------------------------------------------------------------
#define GBM 128
#define GBN 128
#define STAGES 3
#define NTHR 256
#define STAGE_AB (GBM * 128)
#define STAGE_BB (GBN * 128)

__global__ __launch_bounds__(NTHR, 2) void gemm_tc(
    const __half* __restrict__ A, const __half* __restrict__ Bt,
    const float* __restrict__ bias, float* __restrict__ Cf, __half* __restrict__ Ch,
    const float* __restrict__ Radd,
    int M, int N, int K, int relu)
{
    extern __shared__ uint32_t smem[];
    const uint32_t sA_u32 = smem_to_u32(smem);
    const uint32_t sB_u32 = sA_u32 + STAGES * STAGE_AB;

    const int tid  = threadIdx.x;
    const int lane = tid & 31;
    const int wid  = tid >> 5;
    const int wm   = wid >> 2;
    const int wn   = wid & 3;
    const int bm   = blockIdx.y * GBM;
    const int bn   = blockIdx.x * GBN;
    const int nk   = K >> 6;

    int ar[4], ac[4]; uint32_t aso[4];
#pragma unroll
    for (int t = 0; t < 4; t++) {
        int idx = t * NTHR + tid;
        ar[t] = idx >> 3; ac[t] = idx & 7;
        aso[t] = (uint32_t)(ar[t] * 128 + ((ac[t] ^ (ar[t] & 7)) << 4));
    }

    uint32_t aRowB[4], aR7[4];
#pragma unroll
    for (int mf = 0; mf < 4; mf++) {
        int r = wm * 64 + mf * 16 + (lane & 15);
        aRowB[mf] = (uint32_t)r * 128u;
        aR7[mf]   = (uint32_t)(r & 7);
    }
    const uint32_t gselA = (lane >> 4) & 1;
    uint32_t bRowB[2], bR7[2];
#pragma unroll
    for (int np = 0; np < 2; np++) {
        int r = wn * 32 + np * 16 + (lane & 7) + ((lane >> 4) << 3);
        bRowB[np] = (uint32_t)r * 128u;
        bR7[np]   = (uint32_t)(r & 7);
    }
    const uint32_t gselB = (lane >> 3) & 1;

    float acc[4][4][4];
#pragma unroll
    for (int i = 0; i < 4; i++)
#pragma unroll
        for (int j = 0; j < 4; j++)
#pragma unroll
            for (int l = 0; l < 4; l++) acc[i][j][l] = 0.0f;

#define LOAD_STAGE(chunk, stage) do { \
    const int _kc = (chunk) << 6; \
    const uint32_t _sa = sA_u32 + (uint32_t)(stage) * STAGE_AB; \
    const uint32_t _sb = sB_u32 + (uint32_t)(stage) * STAGE_BB; \
    _Pragma("unroll") \
    for (int _t = 0; _t < 4; _t++) \
        cp_async16(_sa + aso[_t], A + (size_t)(bm + ar[_t]) * K + _kc + ac[_t] * 8); \
    _Pragma("unroll") \
    for (int _t = 0; _t < 4; _t++) \
        cp_async16(_sb + aso[_t], Bt + (size_t)(bn + ar[_t]) * K + _kc + ac[_t] * 8); \
    CP_COMMIT(); \
} while (0)

    LOAD_STAGE(0, 0);
    LOAD_STAGE(1, 1);

    int cur = 0, nxt = 2;
    for (int chunk = 0; chunk < nk; chunk++) {
        CP_WAIT(STAGES - 2);
        __syncthreads();

        if (chunk + 2 < nk) {
            LOAD_STAGE(chunk + 2, nxt);
        } else {
            CP_COMMIT();
        }

        const uint32_t saBase = sA_u32 + (uint32_t)cur * STAGE_AB;
        const uint32_t sbBase = sB_u32 + (uint32_t)cur * STAGE_BB;

#pragma unroll
        for (int ks = 0; ks < 4; ks++) {
            const uint32_t gA = 2 * ks + gselA;
            const uint32_t gB = 2 * ks + gselB;
            uint32_t af[4][4];
#pragma unroll
            for (int mf = 0; mf < 4; mf++)
                ldsm_x4(af[mf], saBase + aRowB[mf] + ((gA ^ aR7[mf]) << 4));
            uint32_t bq[2][4];
#pragma unroll
            for (int np = 0; np < 2; np++)
                ldsm_x4(bq[np], sbBase + bRowB[np] + ((gB ^ bR7[np]) << 4));
#pragma unroll
            for (int mf = 0; mf < 4; mf++)
#pragma unroll
                for (int nf = 0; nf < 4; nf++)
                    mma_f16(acc[mf][nf], af[mf], &bq[nf >> 1][(nf & 1) * 2]);
        }
        cur = (cur == 2) ? 0 : cur + 1;
        nxt = (nxt == 2) ? 0 : nxt + 1;
    }

    // ---- epilogue ----
#pragma unroll
    for (int mf = 0; mf < 4; mf++) {
        int row0 = bm + wm * 64 + mf * 16 + (lane >> 2);
#pragma unroll
        for (int nf = 0; nf < 4; nf++) {
            int col = bn + wn * 32 + nf * 8 + (lane & 3) * 2;
            float bx = bias[col], by = bias[col + 1];
            float2 v0, v1;
            v0.x = acc[mf][nf][0] + bx; v0.y = acc[mf][nf][1] + by;
            v1.x = acc[mf][nf][2] + bx; v1.y = acc[mf][nf][3] + by;
            if (relu) {
                v0.x = fmaxf(v0.x, 0.0f); v0.y = fmaxf(v0.y, 0.0f);
                v1.x = fmaxf(v1.x, 0.0f); v1.y = fmaxf(v1.y, 0.0f);
            }
            if (Radd) {
                float2 r0 = *(const float2*)(Radd + (size_t)row0 * N + col);
                float2 r1 = *(const float2*)(Radd + (size_t)(row0 + 8) * N + col);
                v0.x += r0.x; v0.y += r0.y;
                v1.x += r1.x; v1.y += r1.y;
            }
            if (Cf) {
                *(float2*)(Cf + (size_t)row0 * N + col)       = v0;
                *(float2*)(Cf + (size_t)(row0 + 8) * N + col) = v1;
            }
            if (Ch) {
                *(__half2*)(Ch + (size_t)row0 * N + col)       = __floats2half2_rn(v0.x, v0.y);
                *(__half2*)(Ch + (size_t)(row0 + 8) * N + col) = __floats2half2_rn(v1.x, v1.y);
            }
        }
    }
}

// ---------------------------------------------------------------------------
// Kernel: embedding + 2D pos (fp32 + fp16 outputs) and QKV bias concat
// ---------------------------------------------------------------------------
__global__ void embed_kernel(const int* __restrict__ x,
                             const float* __restrict__ tab,
                             const float* __restrict__ rowe,
                             const float* __restrict__ cole,
                             const float* __restrict__ bq,
                             const float* __restrict__ bk,
                             const float* __restrict__ bv,
                             float* __restrict__ h,
                             __half* __restrict__ hh,
                             float* __restrict__ bqkv) {
    int qi = blockIdx.x;
    if (qi >= NTOK) {
        int i = (qi - NTOK) * 128 + threadIdx.x;
        if (i < 3 * D)
            bqkv[i] = (i < D) ? bq[i] : (i < 2 * D) ? bk[i - D] : bv[i - 2 * D];
        return;
    }
    int s  = qi & (SEQ - 1);
    int r  = s >> 5, c = s & 31;
    int tok = x[qi];
    int d = threadIdx.x * 4;

    float4 e = *(const float4*)&tab[(size_t)tok * D + d];
    float4 p;
    if (d < D / 2) p = *(const float4*)&rowe[r * (D / 2) + d];
    else           p = *(const float4*)&cole[c * (D / 2) + (d - D / 2)];
    e.x += p.x; e.y += p.y; e.z += p.z; e.w += p.w;
    *(float4*)&h[(size_t)qi * D + d] = e;
    *(__half2*)&hh[(size_t)qi * D + d]     = __floats2half2_rn(e.x, e.y);
    *(__half2*)&hh[(size_t)qi * D + d + 2] = __floats2half2_rn(e.z, e.w);
}

// ---------------------------------------------------------------------------
// Kernel: fused local-causal attention. 128 threads.
// Scores: fp32 K (float4 loads, q in registers, kid precomputed).
// AV: fp16 V (LDG.64 per key per thread), fp32 accumulation. Output fp16.
// ---------------------------------------------------------------------------
__global__ void attn_kernel(const float* __restrict__ QKV,
                            const __half* __restrict__ QKVh,
                            __half* __restrict__ O) {
    int qi = blockIdx.x;
    int b = qi >> 10, s = qi & (SEQ - 1);
    int r = s >> 5, c = s & 31;
    int r0 = (r - WIN < 0) ? 0 : r - WIN;
    int c0 = (c - WIN < 0) ? 0 : c - WIN;
    int c1 = (c + WIN > 31) ? 31 : c + WIN;
    int wcols = c1 - c0 + 1;
    int nfull = r - r0;
    int nk = nfull * wcols + (c - c0 + 1);

    __shared__ float sc[256];
    __shared__ int   kid[256];
    __shared__ float red[4];

    int tid = threadIdx.x;
    int lane = tid & 31, wid = tid >> 5;

    // Phase 0: parallel kid precompute (kills per-key div/mod in hot loop)
    for (int j = tid; j < nk; j += 128) {
        int row, col;
        if (j < nfull * wcols) { row = r0 + j / wcols; col = c0 + j % wcols; }
        else                   { row = r;             col = c0 + (j - nfull * wcols); }
        kid[j] = row * 32 + col;
    }

    // q into registers: lane owns elements [4*lane + 128*t, +4) for t=0..3
    float4 qr[4];
#pragma unroll
    for (int t = 0; t < 4; t++)
        qr[t] = *(const float4*)&QKV[(size_t)qi * (3 * D) + 4 * lane + 128 * t];

    __syncthreads();   // kid ready

    const float scale = 0.044194173824159216f;
    const float* kbase = QKV + (size_t)b * SEQ * (3 * D) + D;

    // scores: warp w handles keys w, w+4, ... ; 4 independent FMA chains
    for (int j = wid; j < nk; j += 4) {
        const float* krow = kbase + (size_t)kid[j] * (3 * D) + 4 * lane;
        float4 k0 = *(const float4*)(krow);
        float4 k1 = *(const float4*)(krow + 128);
        float4 k2 = *(const float4*)(krow + 256);
        float4 k3 = *(const float4*)(krow + 384);
        float s0 = qr[0].x * k0.x + qr[0].y * k0.y + qr[0].z * k0.z + qr[0].w * k0.w;
        float s1 = qr[1].x * k1.x + qr[1].y * k1.y + qr[1].z * k1.z + qr[1].w * k1.w;
        float s2 = qr[2].x * k2.x + qr[2].y * k2.y + qr[2].z * k2.z + qr[2].w * k2.w;
        float s3 = qr[3].x * k3.x + qr[3].y * k3.y + qr[3].z * k3.z + qr[3].w * k3.w;
        float sum = (s0 + s1) + (s2 + s3);
#pragma unroll
        for (int off = 16; off; off >>= 1)
            sum += __shfl_xor_sync(0xffffffffu, sum, off);
        if (lane == 0) sc[j] = sum * scale;
    }
    __syncthreads();

    // block max
    float m = -1e30f;
    for (int j = tid; j < nk; j += 128) m = fmaxf(m, sc[j]);
#pragma unroll
    for (int off = 16; off; off >>= 1)
        m = fmaxf(m, __shfl_xor_sync(0xffffffffu, m, off));
    if (lane == 0) red[wid] = m;
    __syncthreads();
    m = fmaxf(fmaxf(red[0], red[1]), fmaxf(red[2], red[3]));

    // exp + sum
    float ssum = 0.0f;
    for (int j = tid; j < nk; j += 128) {
        float e = __expf(sc[j] - m);
        sc[j] = e;
        ssum += e;
    }
    __syncthreads();
#pragma unroll
    for (int off = 16; off; off >>= 1)
        ssum += __shfl_xor_sync(0xffffffffu, ssum, off);
    if (lane == 0) red[wid] = ssum;
    __syncthreads();
    float inv = 1.0f / (red[0] + red[1] + red[2] + red[3]);

    // AV: fp16 V, thread owns dims [4*tid, 4*tid+4)
    const __half* vbase = QKVh + (size_t)b * SEQ * (3 * D) + 2 * D;
    int d = tid * 4;
    float4 acc = make_float4(0.f, 0.f, 0.f, 0.f);
    for (int j = 0; j < nk; j++) {
        float w = sc[j];
        const __half* vp = vbase + (size_t)kid[j] * (3 * D) + d;
        __half2 h0 = *(const __half2*)(vp);
        __half2 h1 = *(const __half2*)(vp + 2);
        float2 v0 = __half22float2(h0);
        float2 v1 = __half22float2(h1);
        acc.x = fmaf(w, v0.x, acc.x);
        acc.y = fmaf(w, v0.y, acc.y);
        acc.z = fmaf(w, v1.x, acc.z);
        acc.w = fmaf(w, v1.y, acc.w);
    }
    acc.x *= inv; acc.y *= inv; acc.z *= inv; acc.w *= inv;
    *(__half2*)&O[(size_t)qi * D + d]     = __floats2half2_rn(acc.x, acc.y);
    *(__half2*)&O[(size_t)qi * D + d + 2] = __floats2half2_rn(acc.z, acc.w);
}

// ---------------------------------------------------------------------------
// Kernel: LayerNorm(X) * g + b  ->  fp32 out (optional) + fp16 out (optional)
// ---------------------------------------------------------------------------
__global__ void ln_kernel(const float* __restrict__ X,
                          const float* __restrict__ g,
                          const float* __restrict__ beta,
                          float* __restrict__ outf,
                          __half* __restrict__ outh) {
    int row = blockIdx.x;
    int tid = threadIdx.x;
    int lane = tid & 31, wid = tid >> 5;
    __shared__ float reds[4], redq[4];

    int d = tid * 4;
    float4 xv = *(const float4*)&X[(size_t)row * D + d];

    float s  = xv.x + xv.y + xv.z + xv.w;
    float sq = xv.x * xv.x + xv.y * xv.y + xv.z * xv.z + xv.w * xv.w;
#pragma unroll
    for (int off = 16; off; off >>= 1) {
        s  += __shfl_xor_sync(0xffffffffu, s,  off);
        sq += __shfl_xor_sync(0xffffffffu, sq, off);
    }
    if (lane == 0) { reds[wid] = s; redq[wid] = sq; }
    __syncthreads();
    s  = reds[0] + reds[1] + reds[2] + reds[3];
    sq = redq[0] + redq[1] + redq[2] + redq[3];

    float mu  = s * (1.0f / D);
    float var = sq * (1.0f / D) - mu * mu;
    float rstd = rsqrtf(var + EPS);

    float4 gv = *(const float4*)&g[d];
    float4 bv = *(const float4*)&beta[d];
    float4 o;
    o.x = (xv.x - mu) * rstd * gv.x + bv.x;
    o.y = (xv.y - mu) * rstd * gv.y + bv.y;
    o.z = (xv.z - mu) * rstd * gv.z + bv.z;
    o.w = (xv.w - mu) * rstd * gv.w + bv.w;
    if (outf) *(float4*)&outf[(size_t)row * D + d] = o;
    if (outh) {
        *(__half2*)&outh[(size_t)row * D + d]     = __floats2half2_rn(o.x, o.y);
        *(__half2*)&outh[(size_t)row * D + d + 2] = __floats2half2_rn(o.z, o.w);
    }
}

// ---------------------------------------------------------------------------
// Launch — attn_kernel at launch index 3 for ncu capture.
// ---------------------------------------------------------------------------
extern "C" void kernel_launch(void* const* d_in, const int* in_sizes, int n_in,
                              void* d_out, int out_size) {
    const int*   x     = (const int*)  d_in[0];
    const float* tab   = (const float*)d_in[1];
    const float* rowe  = (const float*)d_in[2];
    const float* cole  = (const float*)d_in[3];
    const float* Wq    = (const float*)d_in[4];
    const float* bq    = (const float*)d_in[5];
    const float* Wk    = (const float*)d_in[6];
    const float* bk    = (const float*)d_in[7];
    const float* Wv    = (const float*)d_in[8];
    const float* bv    = (const float*)d_in[9];
    const float* Wo    = (const float*)d_in[10];
    const float* bo    = (const float*)d_in[11];
    const float* ln1g  = (const float*)d_in[12];
    const float* ln1b  = (const float*)d_in[13];
    const float* W1    = (const float*)d_in[14];
    const float* b1    = (const float*)d_in[15];
    const float* W2    = (const float*)d_in[16];
    const float* b2    = (const float*)d_in[17];
    const float* ln2g  = (const float*)d_in[18];
    const float* ln2b  = (const float*)d_in[19];
    const float* Wh    = (const float*)d_in[20];
    const float* bh    = (const float*)d_in[21];
    float* out = (float*)d_out;

    float *h0, *qkv, *o, *h1, *f, *bqkv;
    __half *h0h, *qkvh, *atth, *h1h, *midh, *h2h;
    __half *Wqkv, *WoT, *W1T, *W2T, *WhT;
    cudaGetSymbolAddress((void**)&h0,   g_h0);
    cudaGetSymbolAddress((void**)&h0h,  g_h0h);
    cudaGetSymbolAddress((void**)&qkv,  g_qkv);
    cudaGetSymbolAddress((void**)&qkvh, g_qkvh);
    cudaGetSymbolAddress((void**)&atth, g_atth);
    cudaGetSymbolAddress((void**)&o,    g_o);
    cudaGetSymbolAddress((void**)&h1,   g_h1);
    cudaGetSymbolAddress((void**)&h1h,  g_h1h);
    cudaGetSymbolAddress((void**)&midh, g_midh);
    cudaGetSymbolAddress((void**)&f,    g_f);
    cudaGetSymbolAddress((void**)&h2h,  g_h2h);
    cudaGetSymbolAddress((void**)&Wqkv, g_Wqkv);
    cudaGetSymbolAddress((void**)&WoT,  g_WoT);
    cudaGetSymbolAddress((void**)&W1T,  g_W1T);
    cudaGetSymbolAddress((void**)&W2T,  g_W2T);
    cudaGetSymbolAddress((void**)&WhT,  g_WhT);
    cudaGetSymbolAddress((void**)&bqkv, g_bqkv);

    const int GEMM_SMEM = STAGES * (STAGE_AB + STAGE_BB);  // 98304 bytes
    static int attr_set = 0;
    if (!attr_set) {
        cudaFuncSetAttribute(gemm_tc, cudaFuncAttributeMaxDynamicSharedMemorySize, GEMM_SMEM);
        attr_set = 1;
    }

    dim3 tb(32, 8);

    // 0: QKV weight transpose
    qkv_transpose<<<dim3(16, 16, 3), tb>>>(Wq, Wk, Wv, Wqkv);
    // 1: embed (+ bias concat)
    embed_kernel<<<NTOK + 12, 128>>>(x, tab, rowe, cole, bq, bk, bv, h0, h0h, bqkv);
    // 2: fused QKV GEMM -> fp32 + fp16 outputs
    gemm_tc<<<dim3(3 * D / GBN, NTOK / GBM), NTHR, GEMM_SMEM>>>(
        h0h, Wqkv, bqkv, qkv, qkvh, nullptr, NTOK, 3 * D, D, 0);
    // 3: attention (profiled)
    attn_kernel<<<NTOK, 128>>>(qkv, qkvh, atth);
    // 4: remaining weight transposes
    prep_weights<<<9472, tb>>>(Wo, W1, W2, Wh, WoT, W1T, W2T, WhT);
    // 5: O projection with fused residual (+ h0)
    gemm_tc<<<dim3(D / GBN, NTOK / GBM), NTHR, GEMM_SMEM>>>(
        atth, WoT, bo, o, nullptr, h0, NTOK, D, D, 0);
    // 6: LN1 -> fp32 h1 (residual for LN2) + fp16 h1h
    ln_kernel<<<NTOK, 128>>>(o, ln1g, ln1b, h1, h1h);
    // 7-8: FFN (FFN2 fuses + h1)
    gemm_tc<<<dim3(DFF / GBN, NTOK / GBM), NTHR, GEMM_SMEM>>>(
        h1h, W1T, b1, nullptr, midh, nullptr, NTOK, DFF, D, 1);
    gemm_tc<<<dim3(D / GBN, NTOK / GBM), NTHR, GEMM_SMEM>>>(
        midh, W2T, b2, f, nullptr, h1, NTOK, D, DFF, 0);
    // 9: LN2 -> fp16 only
    ln_kernel<<<NTOK, 128>>>(f, ln2g, ln2b, nullptr, h2h);
    // 10: vocab head -> d_out
    gemm_tc<<<dim3(VOCAB / GBN, NTOK / GBM), NTHR, GEMM_SMEM>>>(
        h2h, WhT, bh, out, nullptr, nullptr, NTOK, VOCAB, D, 0);
}

// round 17
// speedup vs baseline: 1.1631x; 1.0462x over previous
#include <cuda_runtime.h>
#include <cuda_fp16.h>
#include <math.h>
#include <cstdint>

// ---------------------------------------------------------------------------
// Problem constants
// ---------------------------------------------------------------------------
#define B 8
#define SEQ 1024
#define WIN 9
#define D 512
#define DFF 1024
#define VOCAB 16384
#define NTOK (B * SEQ)   // 8192
#define EPS 1e-5f

// ---------------------------------------------------------------------------
// Scratch buffers (device globals: no allocation allowed)
// ---------------------------------------------------------------------------
__device__ float  g_h0  [NTOK * D];        // embed+pos, fp32 (residual)
__device__ __half g_h0h [NTOK * D];        // fp16 copy (QKV GEMM input)
__device__ __half g_qkvh[NTOK * 3 * D];    // fused QKV output (fp16)
__device__ __half g_atth[NTOK * D];        // attention out (O-proj input)
__device__ float  g_o   [NTOK * D];        // O-proj + h0 (residual fused)
__device__ float  g_h1  [NTOK * D];
__device__ __half g_h1h [NTOK * D];
__device__ __half g_midh[NTOK * DFF];
__device__ float  g_f   [NTOK * D];        // FFN2 + h1 (residual fused)
__device__ __half g_h2h [NTOK * D];
// transposed fp16 weights ([N,K] K-major)
__device__ __half g_Wqkv[3 * D * D];
__device__ __half g_WoT [D * D];
__device__ __half g_W1T [DFF * D];
__device__ __half g_W2T [D * DFF];
__device__ __half g_WhT [VOCAB * D];
__device__ float  g_bqkv[3 * D];

// ---------------------------------------------------------------------------
// helpers (plain compute_103-legal PTX)
// ---------------------------------------------------------------------------
__device__ __forceinline__ uint32_t smem_to_u32(const void* p) {
    uint32_t a;
    asm("{ .reg .u64 t; cvta.to.shared.u64 t, %1; cvt.u32.u64 %0, t; }" : "=r"(a) : "l"(p));
    return a;
}
__device__ __forceinline__ void cp_async16(uint32_t saddr, const void* gptr) {
    asm volatile("cp.async.cg.shared.global [%0], [%1], 16;" :: "r"(saddr), "l"(gptr));
}
#define CP_COMMIT()  asm volatile("cp.async.commit_group;" ::: "memory")
#define CP_WAIT(n)   asm volatile("cp.async.wait_group %0;" :: "n"(n) : "memory")

__device__ __forceinline__ void ldsm_x4(uint32_t* d, uint32_t addr) {
    asm volatile("ldmatrix.sync.aligned.m8n8.x4.shared.b16 {%0,%1,%2,%3}, [%4];"
        : "=r"(d[0]), "=r"(d[1]), "=r"(d[2]), "=r"(d[3]) : "r"(addr));
}
__device__ __forceinline__ void mma_f16(float* d, const uint32_t* a, const uint32_t* b) {
    asm volatile(
        "mma.sync.aligned.m16n8k16.row.col.f32.f16.f16.f32 "
        "{%0,%1,%2,%3}, {%4,%5,%6,%7}, {%8,%9}, {%0,%1,%2,%3};"
        : "+f"(d[0]), "+f"(d[1]), "+f"(d[2]), "+f"(d[3])
        : "r"(a[0]), "r"(a[1]), "r"(a[2]), "r"(a[3]),
          "r"(b[0]), "r"(b[1]));
}

// ---------------------------------------------------------------------------
// Kernel: batched QKV transpose: z selects Wq/Wk/Wv -> Wqkv rows z*D..
// ---------------------------------------------------------------------------
__global__ void qkv_transpose(const float* __restrict__ Wq,
                              const float* __restrict__ Wk,
                              const float* __restrict__ Wv,
                              __half* __restrict__ out) {
    __shared__ float t[32][33];
    const float* in = (blockIdx.z == 0) ? Wq : (blockIdx.z == 1) ? Wk : Wv;
    __half* o = out + (size_t)blockIdx.z * D * D;
    int bx = blockIdx.x * 32, by = blockIdx.y * 32;
    int x = bx + threadIdx.x;
    int y = by + threadIdx.y;
#pragma unroll
    for (int i = 0; i < 32; i += 8)
        t[threadIdx.y + i][threadIdx.x] = in[(size_t)(y + i) * D + x];
    __syncthreads();
    x = by + threadIdx.x;
    y = bx + threadIdx.y;
#pragma unroll
    for (int i = 0; i < 32; i += 8)
        o[(size_t)(y + i) * D + x] = __float2half_rn(t[threadIdx.x][threadIdx.y + i]);
}

// ---------------------------------------------------------------------------
// Kernel: merged weight transposes (Wo, W1, W2, Wh) -> fp16 [N,K]
// ---------------------------------------------------------------------------
__global__ void prep_weights(const float* __restrict__ Wo, const float* __restrict__ W1,
                             const float* __restrict__ W2, const float* __restrict__ Wh,
                             __half* __restrict__ WoT, __half* __restrict__ W1T,
                             __half* __restrict__ W2T, __half* __restrict__ WhT) {
    __shared__ float t[32][33];
    int bid = blockIdx.x;
    const float* in; __half* out; int R, Cn, loc;
    if (bid < 256)       { in = Wo; out = WoT; R = D;   Cn = D;     loc = bid; }
    else if (bid < 768)  { in = W1; out = W1T; R = D;   Cn = DFF;   loc = bid - 256; }
    else if (bid < 1280) { in = W2; out = W2T; R = DFF; Cn = D;     loc = bid - 768; }
    else                 { in = Wh; out = WhT; R = D;   Cn = VOCAB; loc = bid - 1280; }
    int gx = Cn >> 5;
    int bx = (loc % gx) * 32, by = (loc / gx) * 32;
    int x = bx + threadIdx.x;
    int y = by + threadIdx.y;
#pragma unroll
    for (int i = 0; i < 32; i += 8)
        t[threadIdx.y + i][threadIdx.x] = in[(size_t)(y + i) * Cn + x];
    __syncthreads();
    x = by + threadIdx.x;
    y = bx + threadIdx.y;
#pragma unroll
    for (int i = 0; i < 32; i += 8)
        out[(size_t)(y + i) * R + x] = __float2half_rn(t[threadIdx.x][threadIdx.y + i]);
}

// ---------------------------------------------------------------------------
// Kernel: fp16 mma.sync GEMM  C = A @ Bt^T + bias (+ReLU)(+Radd)
// Outputs: Cf (fp32) and/or Ch (fp16) — any non-null gets written.
// ---------------------------------------------------------------------------
#define GBM 128
#define GBN 128
#define STAGES 3
#define NTHR 256
#define STAGE_AB (GBM * 128)
#define STAGE_BB (GBN * 128)

__global__ __launch_bounds__(NTHR, 2) void gemm_tc(
    const __half* __restrict__ A, const __half* __restrict__ Bt,
    const float* __restrict__ bias, float* __restrict__ Cf, __half* __restrict__ Ch,
    const float* __restrict__ Radd,
    int M, int N, int K, int relu)
{
    extern __shared__ uint32_t smem[];
    const uint32_t sA_u32 = smem_to_u32(smem);
    const uint32_t sB_u32 = sA_u32 + STAGES * STAGE_AB;

    const int tid  = threadIdx.x;
    const int lane = tid & 31;
    const int wid  = tid >> 5;
    const int wm   = wid >> 2;
    const int wn   = wid & 3;
    const int bm   = blockIdx.y * GBM;
    const int bn   = blockIdx.x * GBN;
    const int nk   = K >> 6;

    int ar[4], ac[4]; uint32_t aso[4];
#pragma unroll
    for (int t = 0; t < 4; t++) {
        int idx = t * NTHR + tid;
        ar[t] = idx >> 3; ac[t] = idx & 7;
        aso[t] = (uint32_t)(ar[t] * 128 + ((ac[t] ^ (ar[t] & 7)) << 4));
    }

    uint32_t aRowB[4], aR7[4];
#pragma unroll
    for (int mf = 0; mf < 4; mf++) {
        int r = wm * 64 + mf * 16 + (lane & 15);
        aRowB[mf] = (uint32_t)r * 128u;
        aR7[mf]   = (uint32_t)(r & 7);
    }
    const uint32_t gselA = (lane >> 4) & 1;
    uint32_t bRowB[2], bR7[2];
#pragma unroll
    for (int np = 0; np < 2; np++) {
        int r = wn * 32 + np * 16 + (lane & 7) + ((lane >> 4) << 3);
        bRowB[np] = (uint32_t)r * 128u;
        bR7[np]   = (uint32_t)(r & 7);
    }
    const uint32_t gselB = (lane >> 3) & 1;

    float acc[4][4][4];
#pragma unroll
    for (int i = 0; i < 4; i++)
#pragma unroll
        for (int j = 0; j < 4; j++)
#pragma unroll
            for (int l = 0; l < 4; l++) acc[i][j][l] = 0.0f;

#define LOAD_STAGE(chunk, stage) do { \
    const int _kc = (chunk) << 6; \
    const uint32_t _sa = sA_u32 + (uint32_t)(stage) * STAGE_AB; \
    const uint32_t _sb = sB_u32 + (uint32_t)(stage) * STAGE_BB; \
    _Pragma("unroll") \
    for (int _t = 0; _t < 4; _t++) \
        cp_async16(_sa + aso[_t], A + (size_t)(bm + ar[_t]) * K + _kc + ac[_t] * 8); \
    _Pragma("unroll") \
    for (int _t = 0; _t < 4; _t++) \
        cp_async16(_sb + aso[_t], Bt + (size_t)(bn + ar[_t]) * K + _kc + ac[_t] * 8); \
    CP_COMMIT(); \
} while (0)

    LOAD_STAGE(0, 0);
    LOAD_STAGE(1, 1);

    int cur = 0, nxt = 2;
    for (int chunk = 0; chunk < nk; chunk++) {
        CP_WAIT(STAGES - 2);
        __syncthreads();

        if (chunk + 2 < nk) {
            LOAD_STAGE(chunk + 2, nxt);
        } else {
            CP_COMMIT();
        }

        const uint32_t saBase = sA_u32 + (uint32_t)cur * STAGE_AB;
        const uint32_t sbBase = sB_u32 + (uint32_t)cur * STAGE_BB;

#pragma unroll
        for (int ks = 0; ks < 4; ks++) {
            const uint32_t gA = 2 * ks + gselA;
            const uint32_t gB = 2 * ks + gselB;
            uint32_t af[4][4];
#pragma unroll
            for (int mf = 0; mf < 4; mf++)
                ldsm_x4(af[mf], saBase + aRowB[mf] + ((gA ^ aR7[mf]) << 4));
            uint32_t bq[2][4];
#pragma unroll
            for (int np = 0; np < 2; np++)
                ldsm_x4(bq[np], sbBase + bRowB[np] + ((gB ^ bR7[np]) << 4));
#pragma unroll
            for (int mf = 0; mf < 4; mf++)
#pragma unroll
                for (int nf = 0; nf < 4; nf++)
                    mma_f16(acc[mf][nf], af[mf], &bq[nf >> 1][(nf & 1) * 2]);
        }
        cur = (cur == 2) ? 0 : cur + 1;
        nxt = (nxt == 2) ? 0 : nxt + 1;
    }

    // ---- epilogue ----
#pragma unroll
    for (int mf = 0; mf < 4; mf++) {
        int row0 = bm + wm * 64 + mf * 16 + (lane >> 2);
#pragma unroll
        for (int nf = 0; nf < 4; nf++) {
            int col = bn + wn * 32 + nf * 8 + (lane & 3) * 2;
            float bx = bias[col], by = bias[col + 1];
            float2 v0, v1;
            v0.x = acc[mf][nf][0] + bx; v0.y = acc[mf][nf][1] + by;
            v1.x = acc[mf][nf][2] + bx; v1.y = acc[mf][nf][3] + by;
            if (relu) {
                v0.x = fmaxf(v0.x, 0.0f); v0.y = fmaxf(v0.y, 0.0f);
                v1.x = fmaxf(v1.x, 0.0f); v1.y = fmaxf(v1.y, 0.0f);
            }
            if (Radd) {
                float2 r0 = *(const float2*)(Radd + (size_t)row0 * N + col);
                float2 r1 = *(const float2*)(Radd + (size_t)(row0 + 8) * N + col);
                v0.x += r0.x; v0.y += r0.y;
                v1.x += r1.x; v1.y += r1.y;
            }
            if (Cf) {
                *(float2*)(Cf + (size_t)row0 * N + col)       = v0;
                *(float2*)(Cf + (size_t)(row0 + 8) * N + col) = v1;
            }
            if (Ch) {
                *(__half2*)(Ch + (size_t)row0 * N + col)       = __floats2half2_rn(v0.x, v0.y);
                *(__half2*)(Ch + (size_t)(row0 + 8) * N + col) = __floats2half2_rn(v1.x, v1.y);
            }
        }
    }
}

// ---------------------------------------------------------------------------
// Kernel: embedding + 2D pos (fp32 + fp16 outputs) and QKV bias concat
// ---------------------------------------------------------------------------
__global__ void embed_kernel(const int* __restrict__ x,
                             const float* __restrict__ tab,
                             const float* __restrict__ rowe,
                             const float* __restrict__ cole,
                             const float* __restrict__ bq,
                             const float* __restrict__ bk,
                             const float* __restrict__ bv,
                             float* __restrict__ h,
                             __half* __restrict__ hh,
                             float* __restrict__ bqkv) {
    int qi = blockIdx.x;
    if (qi >= NTOK) {
        int i = (qi - NTOK) * 128 + threadIdx.x;
        if (i < 3 * D)
            bqkv[i] = (i < D) ? bq[i] : (i < 2 * D) ? bk[i - D] : bv[i - 2 * D];
        return;
    }
    int s  = qi & (SEQ - 1);
    int r  = s >> 5, c = s & 31;
    int tok = x[qi];
    int d = threadIdx.x * 4;

    float4 e = *(const float4*)&tab[(size_t)tok * D + d];
    float4 p;
    if (d < D / 2) p = *(const float4*)&rowe[r * (D / 2) + d];
    else           p = *(const float4*)&cole[c * (D / 2) + (d - D / 2)];
    e.x += p.x; e.y += p.y; e.z += p.z; e.w += p.w;
    *(float4*)&h[(size_t)qi * D + d] = e;
    *(__half2*)&hh[(size_t)qi * D + d]     = __floats2half2_rn(e.x, e.y);
    *(__half2*)&hh[(size_t)qi * D + d + 2] = __floats2half2_rn(e.z, e.w);
}

// ---------------------------------------------------------------------------
// Kernel: fused local-causal attention, all-fp16 QKV reads. 128 threads.
// Scores: fp16 K via 2x LDG.128/lane/key, fp32 accumulation, q in registers.
// AV: fp16 V (LDG.64/key/thread). Output fp16.
// ---------------------------------------------------------------------------
__global__ void attn_kernel(const __half* __restrict__ QKVh,
                            __half* __restrict__ O) {
    int qi = blockIdx.x;
    int b = qi >> 10, s = qi & (SEQ - 1);
    int r = s >> 5, c = s & 31;
    int r0 = (r - WIN < 0) ? 0 : r - WIN;
    int c0 = (c - WIN < 0) ? 0 : c - WIN;
    int c1 = (c + WIN > 31) ? 31 : c + WIN;
    int wcols = c1 - c0 + 1;
    int nfull = r - r0;
    int nk = nfull * wcols + (c - c0 + 1);

    __shared__ float sc[256];
    __shared__ int   kid[256];
    __shared__ float red[4];

    int tid = threadIdx.x;
    int lane = tid & 31, wid = tid >> 5;

    // Phase 0: parallel kid precompute
    for (int j = tid; j < nk; j += 128) {
        int row, col;
        if (j < nfull * wcols) { row = r0 + j / wcols; col = c0 + j % wcols; }
        else                   { row = r;             col = c0 + (j - nfull * wcols); }
        kid[j] = row * 32 + col;
    }

    // q into fp32 registers: lane owns halves [8*lane + 256*t, +8) for t=0,1
    float qf[16];
    {
        const __half* qrow = QKVh + (size_t)qi * (3 * D) + 8 * lane;
#pragma unroll
        for (int t = 0; t < 2; t++) {
            uint4 qa = *(const uint4*)(qrow + 256 * t);
            const __half2* qh = (const __half2*)&qa;
#pragma unroll
            for (int u = 0; u < 4; u++) {
                float2 f = __half22float2(qh[u]);
                qf[t * 8 + u * 2]     = f.x;
                qf[t * 8 + u * 2 + 1] = f.y;
            }
        }
    }
    __syncthreads();   // kid ready

    const float scale = 0.044194173824159216f;
    const __half* kbase = QKVh + (size_t)b * SEQ * (3 * D) + D;

    // scores: warp w handles keys w, w+4, ...
    for (int j = wid; j < nk; j += 4) {
        const __half* krow = kbase + (size_t)kid[j] * (3 * D) + 8 * lane;
        uint4 ka = *(const uint4*)(krow);
        uint4 kb = *(const uint4*)(krow + 256);
        const __half2* kha = (const __half2*)&ka;
        const __half2* khb = (const __half2*)&kb;
        float s0 = 0.f, s1 = 0.f, s2 = 0.f, s3 = 0.f;
#pragma unroll
        for (int u = 0; u < 4; u++) {
            float2 fa = __half22float2(kha[u]);
            float2 fb = __half22float2(khb[u]);
            s0 = fmaf(qf[u * 2],     fa.x, s0);
            s1 = fmaf(qf[u * 2 + 1], fa.y, s1);
            s2 = fmaf(qf[8 + u * 2],     fb.x, s2);
            s3 = fmaf(qf[8 + u * 2 + 1], fb.y, s3);
        }
        float sum = (s0 + s1) + (s2 + s3);
#pragma unroll
        for (int off = 16; off; off >>= 1)
            sum += __shfl_xor_sync(0xffffffffu, sum, off);
        if (lane == 0) sc[j] = sum * scale;
    }
    __syncthreads();

    // block max
    float m = -1e30f;
    for (int j = tid; j < nk; j += 128) m = fmaxf(m, sc[j]);
#pragma unroll
    for (int off = 16; off; off >>= 1)
        m = fmaxf(m, __shfl_xor_sync(0xffffffffu, m, off));
    if (lane == 0) red[wid] = m;
    __syncthreads();
    m = fmaxf(fmaxf(red[0], red[1]), fmaxf(red[2], red[3]));

    // exp + sum
    float ssum = 0.0f;
    for (int j = tid; j < nk; j += 128) {
        float e = __expf(sc[j] - m);
        sc[j] = e;
        ssum += e;
    }
    __syncthreads();
#pragma unroll
    for (int off = 16; off; off >>= 1)
        ssum += __shfl_xor_sync(0xffffffffu, ssum, off);
    if (lane == 0) red[wid] = ssum;
    __syncthreads();
    float inv = 1.0f / (red[0] + red[1] + red[2] + red[3]);

    // AV: fp16 V, thread owns dims [4*tid, 4*tid+4)
    const __half* vbase = QKVh + (size_t)b * SEQ * (3 * D) + 2 * D;
    int d = tid * 4;
    float4 acc = make_float4(0.f, 0.f, 0.f, 0.f);
    for (int j = 0; j < nk; j++) {
        float w = sc[j];
        const __half* vp = vbase + (size_t)kid[j] * (3 * D) + d;
        __half2 h0 = *(const __half2*)(vp);
        __half2 h1 = *(const __half2*)(vp + 2);
        float2 v0 = __half22float2(h0);
        float2 v1 = __half22float2(h1);
        acc.x = fmaf(w, v0.x, acc.x);
        acc.y = fmaf(w, v0.y, acc.y);
        acc.z = fmaf(w, v1.x, acc.z);
        acc.w = fmaf(w, v1.y, acc.w);
    }
    acc.x *= inv; acc.y *= inv; acc.z *= inv; acc.w *= inv;
    *(__half2*)&O[(size_t)qi * D + d]     = __floats2half2_rn(acc.x, acc.y);
    *(__half2*)&O[(size_t)qi * D + d + 2] = __floats2half2_rn(acc.z, acc.w);
}

// ---------------------------------------------------------------------------
// Kernel: LayerNorm(X) * g + b  ->  fp32 out (optional) + fp16 out (optional)
// ---------------------------------------------------------------------------
__global__ void ln_kernel(const float* __restrict__ X,
                          const float* __restrict__ g,
                          const float* __restrict__ beta,
                          float* __restrict__ outf,
                          __half* __restrict__ outh) {
    int row = blockIdx.x;
    int tid = threadIdx.x;
    int lane = tid & 31, wid = tid >> 5;
    __shared__ float reds[4], redq[4];

    int d = tid * 4;
    float4 xv = *(const float4*)&X[(size_t)row * D + d];

    float s  = xv.x + xv.y + xv.z + xv.w;
    float sq = xv.x * xv.x + xv.y * xv.y + xv.z * xv.z + xv.w * xv.w;
#pragma unroll
    for (int off = 16; off; off >>= 1) {
        s  += __shfl_xor_sync(0xffffffffu, s,  off);
        sq += __shfl_xor_sync(0xffffffffu, sq, off);
    }
    if (lane == 0) { reds[wid] = s; redq[wid] = sq; }
    __syncthreads();
    s  = reds[0] + reds[1] + reds[2] + reds[3];
    sq = redq[0] + redq[1] + redq[2] + redq[3];

    float mu  = s * (1.0f / D);
    float var = sq * (1.0f / D) - mu * mu;
    float rstd = rsqrtf(var + EPS);

    float4 gv = *(const float4*)&g[d];
    float4 bv = *(const float4*)&beta[d];
    float4 o;
    o.x = (xv.x - mu) * rstd * gv.x + bv.x;
    o.y = (xv.y - mu) * rstd * gv.y + bv.y;
    o.z = (xv.z - mu) * rstd * gv.z + bv.z;
    o.w = (xv.w - mu) * rstd * gv.w + bv.w;
    if (outf) *(float4*)&outf[(size_t)row * D + d] = o;
    if (outh) {
        *(__half2*)&outh[(size_t)row * D + d]     = __floats2half2_rn(o.x, o.y);
        *(__half2*)&outh[(size_t)row * D + d + 2] = __floats2half2_rn(o.z, o.w);
    }
}

// ---------------------------------------------------------------------------
// Launch — attn_kernel at launch index 3 for ncu capture.
// ---------------------------------------------------------------------------
extern "C" void kernel_launch(void* const* d_in, const int* in_sizes, int n_in,
                              void* d_out, int out_size) {
    const int*   x     = (const int*)  d_in[0];
    const float* tab   = (const float*)d_in[1];
    const float* rowe  = (const float*)d_in[2];
    const float* cole  = (const float*)d_in[3];
    const float* Wq    = (const float*)d_in[4];
    const float* bq    = (const float*)d_in[5];
    const float* Wk    = (const float*)d_in[6];
    const float* bk    = (const float*)d_in[7];
    const float* Wv    = (const float*)d_in[8];
    const float* bv    = (const float*)d_in[9];
    const float* Wo    = (const float*)d_in[10];
    const float* bo    = (const float*)d_in[11];
    const float* ln1g  = (const float*)d_in[12];
    const float* ln1b  = (const float*)d_in[13];
    const float* W1    = (const float*)d_in[14];
    const float* b1    = (const float*)d_in[15];
    const float* W2    = (const float*)d_in[16];
    const float* b2    = (const float*)d_in[17];
    const float* ln2g  = (const float*)d_in[18];
    const float* ln2b  = (const float*)d_in[19];
    const float* Wh    = (const float*)d_in[20];
    const float* bh    = (const float*)d_in[21];
    float* out = (float*)d_out;

    float *h0, *o, *h1, *f, *bqkv;
    __half *h0h, *qkvh, *atth, *h1h, *midh, *h2h;
    __half *Wqkv, *WoT, *W1T, *W2T, *WhT;
    cudaGetSymbolAddress((void**)&h0,   g_h0);
    cudaGetSymbolAddress((void**)&h0h,  g_h0h);
    cudaGetSymbolAddress((void**)&qkvh, g_qkvh);
    cudaGetSymbolAddress((void**)&atth, g_atth);
    cudaGetSymbolAddress((void**)&o,    g_o);
    cudaGetSymbolAddress((void**)&h1,   g_h1);
    cudaGetSymbolAddress((void**)&h1h,  g_h1h);
    cudaGetSymbolAddress((void**)&midh, g_midh);
    cudaGetSymbolAddress((void**)&f,    g_f);
    cudaGetSymbolAddress((void**)&h2h,  g_h2h);
    cudaGetSymbolAddress((void**)&Wqkv, g_Wqkv);
    cudaGetSymbolAddress((void**)&WoT,  g_WoT);
    cudaGetSymbolAddress((void**)&W1T,  g_W1T);
    cudaGetSymbolAddress((void**)&W2T,  g_W2T);
    cudaGetSymbolAddress((void**)&WhT,  g_WhT);
    cudaGetSymbolAddress((void**)&bqkv, g_bqkv);

    const int GEMM_SMEM = STAGES * (STAGE_AB + STAGE_BB);  // 98304 bytes
    static int attr_set = 0;
    if (!attr_set) {
        cudaFuncSetAttribute(gemm_tc, cudaFuncAttributeMaxDynamicSharedMemorySize, GEMM_SMEM);
        attr_set = 1;
    }

    dim3 tb(32, 8);

    // 0: QKV weight transpose
    qkv_transpose<<<dim3(16, 16, 3), tb>>>(Wq, Wk, Wv, Wqkv);
    // 1: embed (+ bias concat)
    embed_kernel<<<NTOK + 12, 128>>>(x, tab, rowe, cole, bq, bk, bv, h0, h0h, bqkv);
    // 2: fused QKV GEMM -> fp16 output only
    gemm_tc<<<dim3(3 * D / GBN, NTOK / GBM), NTHR, GEMM_SMEM>>>(
        h0h, Wqkv, bqkv, nullptr, qkvh, nullptr, NTOK, 3 * D, D, 0);
    // 3: attention (profiled) — all-fp16 QKV reads
    attn_kernel<<<NTOK, 128>>>(qkvh, atth);
    // 4: remaining weight transposes
    prep_weights<<<9472, tb>>>(Wo, W1, W2, Wh, WoT, W1T, W2T, WhT);
    // 5: O projection with fused residual (+ h0)
    gemm_tc<<<dim3(D / GBN, NTOK / GBM), NTHR, GEMM_SMEM>>>(
        atth, WoT, bo, o, nullptr, h0, NTOK, D, D, 0);
    // 6: LN1 -> fp32 h1 (residual for LN2) + fp16 h1h
    ln_kernel<<<NTOK, 128>>>(o, ln1g, ln1b, h1, h1h);
    // 7-8: FFN (FFN2 fuses + h1)
    gemm_tc<<<dim3(DFF / GBN, NTOK / GBM), NTHR, GEMM_SMEM>>>(
        h1h, W1T, b1, nullptr, midh, nullptr, NTOK, DFF, D, 1);
    gemm_tc<<<dim3(D / GBN, NTOK / GBM), NTHR, GEMM_SMEM>>>(
        midh, W2T, b2, f, nullptr, h1, NTOK, D, DFF, 0);
    // 9: LN2 -> fp16 only
    ln_kernel<<<NTOK, 128>>>(f, ln2g, ln2b, nullptr, h2h);
    // 10: vocab head -> d_out
    gemm_tc<<<dim3(VOCAB / GBN, NTOK / GBM), NTHR, GEMM_SMEM>>>(
        h2h, WhT, bh, out, nullptr, nullptr, NTOK, VOCAB, D, 0);
}